// round 15
// baseline (speedup 1.0000x reference)
#include <cuda_runtime.h>

// TemporalTransformerBlock, fp32 + Blackwell packed f32x2, token-packed.
// 65536 seqs, T=24, D=16, NH=4, HD=4, DFF=64, 2 layers.
// 12 threads/sequence, 2 tokens/thread. Activations stored as token-pairs:
// h[d] = (h_tok0[d], h_tok1[d]). GEMM weights pre-DUPLICATED in smem so
// every GEMM is pure pfma with bias-pair accumulator init: no horizontal
// adds anywhere outside attention. Attention itself is the proven R3 form.

namespace {
constexpr int HW   = 256 * 256;
constexpr int T    = 24;
constexpr int D    = 16;
constexpr int NH   = 4;
constexpr int DFF  = 64;
constexpr int NL   = 2;
constexpr int S    = 16;          // sequences per block
constexpr int TPS  = 12;          // threads per sequence
constexpr int NT   = S * TPS;     // 192

constexpr float QSCALE = 0.7213475204444817f;   // 0.5 * log2(e)

// ---- shared-memory float offsets (all LDS.128 targets 16B aligned) ----
constexpr int OFF_WQKVD = 0;        // 96 rows x 32 (dup)        = 3072
constexpr int OFF_BQKVD = 3072;     // 96 pairs                  = 192
constexpr int OFF_WOD   = 3264;     // 32 rows x 32              = 1024
constexpr int OFF_BOD   = 4288;     // 32 pairs                  = 64
constexpr int OFF_W1D   = 4352;     // 128 rows x 32             = 4096
constexpr int OFF_B1D   = 8448;     // 128 pairs                 = 256
constexpr int OFF_W2TD  = 8704;     // 128 rows x 32 (transposed+dup) = 4096
constexpr int OFF_B2D   = 12800;    // 32 pairs                  = 64
constexpr int OFF_LN1WD = 12864;    // 64
constexpr int OFF_LN1BD = 12928;    // 64
constexpr int OFF_LN2WD = 12992;    // 64
constexpr int OFF_LN2BD = 13056;    // 64
constexpr int OFF_WIND  = 13120;    // 32
constexpr int OFF_BIND  = 13152;    // 32
constexpr int OFF_WOUTD = 13184;    // 32
constexpr int OFF_BOUT  = 13216;    // 2 (+2 pad)
constexpr int OFF_XS    = 13220;    // 24*17 = 408
// K/V SoA per sequence: row = head*4+d (16 rows), column = token s.
constexpr int SROW = 26;
constexpr int KSEQ = 16 * SROW + 8;             // 424
constexpr int OFF_K = 13628;                    // even
constexpr int OFF_V = OFF_K + S * KSEQ;         // 20412
constexpr int SMEM_FLOATS = OFF_V + S * KSEQ;   // 27196
constexpr int SMEM_BYTES  = SMEM_FLOATS * 4;    // 108784
}

using u64 = unsigned long long;

__device__ __forceinline__ u64 pk(float lo, float hi) {
    u64 r; asm("mov.b64 %0, {%1, %2};" : "=l"(r) : "f"(lo), "f"(hi)); return r;
}
__device__ __forceinline__ void unpk(u64 p, float& lo, float& hi) {
    asm("mov.b64 {%0, %1}, %2;" : "=f"(lo), "=f"(hi) : "l"(p));
}
__device__ __forceinline__ u64 pfma(u64 a, u64 b, u64 c) {
    u64 d; asm("fma.rn.f32x2 %0, %1, %2, %3;" : "=l"(d) : "l"(a), "l"(b), "l"(c));
    return d;
}
__device__ __forceinline__ u64 padd(u64 a, u64 b) {
    u64 d; asm("add.rn.f32x2 %0, %1, %2;" : "=l"(d) : "l"(a), "l"(b)); return d;
}
__device__ __forceinline__ u64 pmul(u64 a, u64 b) {
    u64 d; asm("mul.rn.f32x2 %0, %1, %2;" : "=l"(d) : "l"(a), "l"(b)); return d;
}
__device__ __forceinline__ float hadd(u64 p) {
    float lo, hi; unpk(p, lo, hi); return lo + hi;
}
__device__ __forceinline__ float ex2f(float x) {
    float r; asm("ex2.approx.f32 %0, %1;" : "=f"(r) : "f"(x)); return r;
}
__device__ __forceinline__ float rcpf(float x) {
    float r; asm("rcp.approx.f32 %0, %1;" : "=f"(r) : "f"(x)); return r;
}

// token-packed dot: acc(pair over tokens) = bias_pair + sum_d h[d]*wdup[d].
// wdup row = 32 floats (16 dup pairs), bias = 2 floats (dup pair).
__device__ __forceinline__ u64 dotTP(const u64* h, const float* wdup,
                                     const float* bdup) {
    const ulonglong2* w2 = reinterpret_cast<const ulonglong2*>(wdup);
    u64 acc = *reinterpret_cast<const u64*>(bdup);
#pragma unroll
    for (int c = 0; c < 8; c++) {
        ulonglong2 wv = w2[c];
        acc = pfma(h[2*c],   wv.x, acc);
        acc = pfma(h[2*c+1], wv.y, acc);
    }
    return acc;
}

// token-packed LayerNorm over 16 token-pairs (both tokens at once).
__device__ __forceinline__ void lnTP(const u64* y, const float* gdup,
                                     const float* bdup, u64* o) {
    u64 s = padd(padd(padd(y[0], y[1]),  padd(y[2], y[3])),
                 padd(padd(y[4], y[5]),  padd(y[6], y[7])));
    s = padd(s, padd(padd(padd(y[8], y[9]),   padd(y[10], y[11])),
                     padd(padd(y[12], y[13]), padd(y[14], y[15]))));
    u64 nmu = pmul(s, pk(-0.0625f, -0.0625f));   // -(mean) per lane
    u64 c[16];
    u64 v = 0ull;
#pragma unroll
    for (int d = 0; d < 16; d++) {
        c[d] = padd(y[d], nmu);
        v = pfma(c[d], c[d], v);
    }
    float v0, v1; unpk(v, v0, v1);
    float rs0 = rsqrtf(fmaf(v0, 0.0625f, 1e-5f));
    float rs1 = rsqrtf(fmaf(v1, 0.0625f, 1e-5f));
    u64 rs = pk(rs0, rs1);
    const ulonglong2* g2 = reinterpret_cast<const ulonglong2*>(gdup);
    const ulonglong2* b2 = reinterpret_cast<const ulonglong2*>(bdup);
#pragma unroll
    for (int q = 0; q < 8; q++) {
        ulonglong2 gv = g2[q], bv = b2[q];
        o[2*q]   = pfma(pmul(c[2*q],   rs), gv.x, bv.x);
        o[2*q+1] = pfma(pmul(c[2*q+1], rs), gv.y, bv.y);
    }
}

__global__ __launch_bounds__(NT, 2)
void ttb_kernel(const float* __restrict__ x,
                const float* __restrict__ Win,  const float* __restrict__ binp,
                const float* __restrict__ Wqkv, const float* __restrict__ bqkv,
                const float* __restrict__ Wo,   const float* __restrict__ bo,
                const float* __restrict__ ln1w, const float* __restrict__ ln1b,
                const float* __restrict__ W1,   const float* __restrict__ b1,
                const float* __restrict__ W2,   const float* __restrict__ b2,
                const float* __restrict__ ln2w, const float* __restrict__ ln2b,
                const float* __restrict__ Wout, const float* __restrict__ bout,
                float* __restrict__ out) {
    extern __shared__ float sm[];
    const int tid = threadIdx.x;

    // ---- stage weights, DUPLICATED per element; Q rows pre-scaled ----
    for (int i = tid; i < 3072; i += NT) {          // Wqkv: rows l*48+o
        int row = i >> 5, d = (i & 31) >> 1;
        float wv = Wqkv[row * 16 + d];
        if ((row % 48) < 16) wv *= QSCALE;
        sm[OFF_WQKVD + i] = wv;
    }
    for (int i = tid; i < 192; i += NT) {
        int idx = i >> 1;
        float b = bqkv[idx];
        if ((idx % 48) < 16) b *= QSCALE;
        sm[OFF_BQKVD + i] = b;
    }
    for (int i = tid; i < 1024; i += NT)
        sm[OFF_WOD + i] = Wo[(i >> 5) * 16 + ((i & 31) >> 1)];
    for (int i = tid; i < 64; i += NT) sm[OFF_BOD + i] = bo[i >> 1];
    for (int i = tid; i < 4096; i += NT)
        sm[OFF_W1D + i] = W1[(i >> 5) * 16 + ((i & 31) >> 1)];
    for (int i = tid; i < 256; i += NT) sm[OFF_B1D + i] = b1[i >> 1];
    for (int i = tid; i < 4096; i += NT) {          // W2 [l][d][o] -> dup [l][o][2d]
        int row = i >> 5, l = row >> 6, o = row & 63, d = (i & 31) >> 1;
        sm[OFF_W2TD + i] = W2[l * 1024 + d * 64 + o];
    }
    for (int i = tid; i < 64; i += NT) sm[OFF_B2D + i] = b2[i >> 1];
    for (int i = tid; i < 64; i += NT) sm[OFF_LN1WD + i] = ln1w[i >> 1];
    for (int i = tid; i < 64; i += NT) sm[OFF_LN1BD + i] = ln1b[i >> 1];
    for (int i = tid; i < 64; i += NT) sm[OFF_LN2WD + i] = ln2w[i >> 1];
    for (int i = tid; i < 64; i += NT) sm[OFF_LN2BD + i] = ln2b[i >> 1];
    for (int i = tid; i < 32; i += NT) sm[OFF_WIND + i] = Win[i >> 1];
    for (int i = tid; i < 32; i += NT) sm[OFF_BIND + i] = binp[i >> 1];
    for (int i = tid; i < 32; i += NT) sm[OFF_WOUTD + i] = Wout[i >> 1];
    if (tid == 0) { sm[OFF_BOUT] = bout[0]; sm[OFF_BOUT + 1] = bout[0]; }

    // ---- stage this block's input pixels ----
    const int n0 = blockIdx.x * S;
    for (int i = tid; i < T * S; i += NT) {
        int t = i >> 4, c = i & 15;
        sm[OFF_XS + t * 17 + c] = x[t * HW + n0 + c];
    }
    __syncthreads();

    const int sl = tid / TPS;
    const int r  = tid % TPS;
    const int n  = n0 + sl;
    const int t0 = 2 * r;                 // tokens t0, t0+1

    // ---- input projection: h[d] = (x_t0, x_t1)*Win[d] + bin[d] ----
    u64 h[16];
    {
        float xv0 = sm[OFF_XS + t0 * 17 + sl];
        float xv1 = sm[OFF_XS + (t0 + 1) * 17 + sl];
        u64 xp = pk(xv0, xv1);
        const ulonglong2* wiv = reinterpret_cast<const ulonglong2*>(&sm[OFF_WIND]);
        const ulonglong2* biv = reinterpret_cast<const ulonglong2*>(&sm[OFF_BIND]);
#pragma unroll
        for (int c = 0; c < 8; c++) {
            ulonglong2 wv = wiv[c], bv = biv[c];
            h[2*c]   = pfma(xp, wv.x, bv.x);
            h[2*c+1] = pfma(xp, wv.y, bv.y);
        }
    }

    float* ksh = &sm[OFF_K + sl * KSEQ];
    float* vsh = &sm[OFF_V + sl * KSEQ];

#pragma unroll 1
    for (int l = 0; l < NL; l++) {
        const float* wqkvD = &sm[OFF_WQKVD + l * 1536];
        const float* bqD   = &sm[OFF_BQKVD + l * 96];
        const float* woD   = &sm[OFF_WOD   + l * 512];
        const float* boD   = &sm[OFF_BOD   + l * 32];
        const float* w1D   = &sm[OFF_W1D   + l * 2048];
        const float* b1D   = &sm[OFF_B1D   + l * 128];
        const float* w2tD  = &sm[OFF_W2TD  + l * 2048];
        const float* b2D   = &sm[OFF_B2D   + l * 32];
        const float* g1wD  = &sm[OFF_LN1WD + l * 32];
        const float* g1bD  = &sm[OFF_LN1BD + l * 32];
        const float* g2wD  = &sm[OFF_LN2WD + l * 32];
        const float* g2bD  = &sm[OFF_LN2BD + l * 32];

        // ---- K,V projection -> SoA shared; pair (t0,t1) stored directly ----
#pragma unroll 4
        for (int o = 0; o < D; o++) {         // K = qkv outputs 16..31
            u64 acc = dotTP(h, wqkvD + (D + o) * 32, bqD + (D + o) * 2);
            *reinterpret_cast<u64*>(&ksh[o * SROW + t0]) = acc;
        }
#pragma unroll 4
        for (int o = 0; o < D; o++) {         // V = qkv outputs 32..47
            u64 acc = dotTP(h, wqkvD + (2 * D + o) * 32, bqD + (2 * D + o) * 2);
            *reinterpret_cast<u64*>(&vsh[o * SROW + t0]) = acc;
        }
        __syncthreads();

        // ---- attention (R3 structure); ctx assembled token-packed ----
        u64 ct[16];
#pragma unroll
        for (int hd = 0; hd < NH; hd++) {
            // q as token-pairs via packed GEMM (Q weights pre-scaled)
            u64 qp0[4], qp1[4];
#pragma unroll
            for (int d4 = 0; d4 < 4; d4++) {
                u64 q = dotTP(h, wqkvD + (4 * hd + d4) * 32, bqD + (4 * hd + d4) * 2);
                float qa, qb; unpk(q, qa, qb);
                qp0[d4] = pk(qa, qa);
                qp1[d4] = pk(qb, qb);
            }
            const float* kb = ksh + hd * (4 * SROW);
            const float* vb = vsh + hd * (4 * SROW);
            float vt0[4], vt1[4];
#pragma unroll
            for (int j = 0; j < 2; j++) {
                const u64* qp = j ? qp1 : qp0;
                u64 lg[T / 2];
#pragma unroll
                for (int sp = 0; sp < T / 2; sp++) {
                    u64 k0 = *reinterpret_cast<const u64*>(kb + 2 * sp);
                    u64 k1 = *reinterpret_cast<const u64*>(kb + SROW + 2 * sp);
                    u64 k2 = *reinterpret_cast<const u64*>(kb + 2 * SROW + 2 * sp);
                    u64 k3 = *reinterpret_cast<const u64*>(kb + 3 * SROW + 2 * sp);
                    lg[sp] = pfma(qp[0], k0, pfma(qp[1], k1, pfma(qp[2], k2, pmul(qp[3], k3))));
                }
                // softmax in base-2, no max-subtraction (tiny logits)
                u64 s2 = 0ull;
#pragma unroll
                for (int sp = 0; sp < T / 2; sp++) {
                    float a, b; unpk(lg[sp], a, b);
                    u64 e = pk(ex2f(a), ex2f(b));
                    lg[sp] = e;
                    s2 = padd(s2, e);
                }
                float inv = rcpf(hadd(s2));
                u64 a0 = 0ull, a1 = 0ull, a2 = 0ull, a3 = 0ull;
#pragma unroll
                for (int sp = 0; sp < T / 2; sp++) {
                    u64 v0 = *reinterpret_cast<const u64*>(vb + 2 * sp);
                    u64 v1 = *reinterpret_cast<const u64*>(vb + SROW + 2 * sp);
                    u64 v2 = *reinterpret_cast<const u64*>(vb + 2 * SROW + 2 * sp);
                    u64 v3 = *reinterpret_cast<const u64*>(vb + 3 * SROW + 2 * sp);
                    a0 = pfma(lg[sp], v0, a0);
                    a1 = pfma(lg[sp], v1, a1);
                    a2 = pfma(lg[sp], v2, a2);
                    a3 = pfma(lg[sp], v3, a3);
                }
                float* vt = j ? vt1 : vt0;
                vt[0] = hadd(a0) * inv;
                vt[1] = hadd(a1) * inv;
                vt[2] = hadd(a2) * inv;
                vt[3] = hadd(a3) * inv;
            }
            ct[4*hd + 0] = pk(vt0[0], vt1[0]);
            ct[4*hd + 1] = pk(vt0[1], vt1[1]);
            ct[4*hd + 2] = pk(vt0[2], vt1[2]);
            ct[4*hd + 3] = pk(vt0[3], vt1[3]);
        }

        // ---- Wo + residual + LN1 (all token-packed, no hadds) ----
        {
            u64 y[16];
#pragma unroll 4
            for (int o = 0; o < D; o++) {
                u64 acc = dotTP(ct, woD + o * 32, boD + o * 2);
                y[o] = padd(h[o], acc);
            }
            lnTP(y, g1wD, g1bD, h);
        }

        // ---- FFN (token-packed, no hadds) ----
        {
            u64 f[16];
            const u64* b2p = reinterpret_cast<const u64*>(b2D);
#pragma unroll
            for (int d = 0; d < 16; d++) f[d] = b2p[d];
#pragma unroll 2
            for (int o = 0; o < DFF; o++) {
                u64 u = dotTP(h, w1D + o * 32, b1D + o * 2);
                float ua, ub; unpk(u, ua, ub);
                u = pk(fmaxf(ua, 0.f), fmaxf(ub, 0.f));
                const ulonglong2* wr =
                    reinterpret_cast<const ulonglong2*>(w2tD + o * 32);
#pragma unroll
                for (int c = 0; c < 8; c++) {
                    ulonglong2 wv = wr[c];
                    f[2*c]   = pfma(u, wv.x, f[2*c]);
                    f[2*c+1] = pfma(u, wv.y, f[2*c+1]);
                }
            }
            u64 y[16];
#pragma unroll
            for (int d = 0; d < 16; d++) y[d] = padd(h[d], f[d]);
            lnTP(y, g2wD, g2bD, h);
        }
        __syncthreads();   // K/V reuse by next layer
    }

    // ---- output projection (token-pair result) ----
    {
        u64 acc = dotTP(h, &sm[OFF_WOUTD], &sm[OFF_BOUT]);
        float o0, o1; unpk(acc, o0, o1);
        out[t0 * HW + n]       = o0;
        out[(t0 + 1) * HW + n] = o1;
    }
}

extern "C" void kernel_launch(void* const* d_in, const int* in_sizes, int n_in,
                              void* d_out, int out_size) {
    (void)in_sizes; (void)n_in; (void)out_size;
    cudaFuncSetAttribute(ttb_kernel, cudaFuncAttributeMaxDynamicSharedMemorySize,
                         SMEM_BYTES);
    ttb_kernel<<<HW / S, NT, SMEM_BYTES>>>(
        (const float*)d_in[0],  (const float*)d_in[1],  (const float*)d_in[2],
        (const float*)d_in[3],  (const float*)d_in[4],  (const float*)d_in[5],
        (const float*)d_in[6],  (const float*)d_in[7],  (const float*)d_in[8],
        (const float*)d_in[9],  (const float*)d_in[10], (const float*)d_in[11],
        (const float*)d_in[12], (const float*)d_in[13], (const float*)d_in[14],
        (const float*)d_in[15], (const float*)d_in[16],
        (float*)d_out);
}

// round 16
// speedup vs baseline: 1.2614x; 1.2614x over previous
#include <cuda_runtime.h>

// TemporalTransformerBlock, fp32 + Blackwell packed f32x2.
// 65536 seqs, T=24, D=16, NH=4, HD=4, DFF=64, 2 layers.
// 12 threads/sequence, 2 tokens/thread; weights in smem (broadcast LDS);
// K/V SoA in smem with 16B-aligned rows, read ROW-MAJOR as LDS.128
// (halves attention LDS instruction count vs column-wise LDS.64).

namespace {
constexpr int HW   = 256 * 256;
constexpr int T    = 24;
constexpr int D    = 16;
constexpr int NH   = 4;
constexpr int DFF  = 64;
constexpr int NL   = 2;
constexpr int S    = 16;          // sequences per block
constexpr int TPS  = 12;          // threads per sequence
constexpr int NT   = S * TPS;     // 192

constexpr float QSCALE = 0.7213475204444817f;   // 0.5 * log2(e)

// shared-memory float offsets
constexpr int OFF_WQKV = 0;                     // 1536
constexpr int OFF_BQKV = 1536;                  // 96
constexpr int OFF_WO   = 1632;                  // 512
constexpr int OFF_BO   = 2144;                  // 32
constexpr int OFF_W1   = 2176;                  // 2048
constexpr int OFF_B1   = 4224;                  // 128
constexpr int OFF_W2T  = 4352;                  // 2048 (W2 transposed [o][d])
constexpr int OFF_B2   = 6400;                  // 32
constexpr int OFF_LN1W = 6432;                  // 32
constexpr int OFF_LN1B = 6464;                  // 32
constexpr int OFF_LN2W = 6496;                  // 32
constexpr int OFF_LN2B = 6528;                  // 32
constexpr int OFF_WIN  = 6560;                  // 16
constexpr int OFF_BIN  = 6576;                  // 16
constexpr int OFF_WOUT = 6592;                  // 16
constexpr int OFF_BOUT = 6608;                  // 1 (+3 pad)
constexpr int OFF_XS   = 6612;                  // 24*17 = 408

// K/V SoA per sequence: row = head*4+d (16 rows), column = token s.
// SROW=28 -> each row base 16B-aligned (28*4=112B, rows start multiple of 16).
constexpr int SROW = 28;
constexpr int KSEQ = 16 * SROW + 4;             // 452 (x4B=1808, 16B aligned)
constexpr int OFF_K = 7020;                     // x4=28080, 16B aligned
constexpr int OFF_V = OFF_K + S * KSEQ;         // 14252
constexpr int SMEM_FLOATS = OFF_V + S * KSEQ;   // 21484
constexpr int SMEM_BYTES  = SMEM_FLOATS * 4;    // 85936
}

using u64 = unsigned long long;

__device__ __forceinline__ u64 pk(float lo, float hi) {
    u64 r; asm("mov.b64 %0, {%1, %2};" : "=l"(r) : "f"(lo), "f"(hi)); return r;
}
__device__ __forceinline__ void unpk(u64 p, float& lo, float& hi) {
    asm("mov.b64 {%0, %1}, %2;" : "=f"(lo), "=f"(hi) : "l"(p));
}
__device__ __forceinline__ u64 pfma(u64 a, u64 b, u64 c) {
    u64 d; asm("fma.rn.f32x2 %0, %1, %2, %3;" : "=l"(d) : "l"(a), "l"(b), "l"(c));
    return d;
}
__device__ __forceinline__ u64 padd(u64 a, u64 b) {
    u64 d; asm("add.rn.f32x2 %0, %1, %2;" : "=l"(d) : "l"(a), "l"(b)); return d;
}
__device__ __forceinline__ u64 pmul(u64 a, u64 b) {
    u64 d; asm("mul.rn.f32x2 %0, %1, %2;" : "=l"(d) : "l"(a), "l"(b)); return d;
}
__device__ __forceinline__ float hadd(u64 p) {
    float lo, hi; unpk(p, lo, hi); return lo + hi;
}
__device__ __forceinline__ float ex2f(float x) {
    float r; asm("ex2.approx.f32 %0, %1;" : "=f"(r) : "f"(x)); return r;
}
__device__ __forceinline__ float rcpf(float x) {
    float r; asm("rcp.approx.f32 %0, %1;" : "=f"(r) : "f"(x)); return r;
}

// two 16-dots (both tokens) against one shared weight row (LDS.128 broadcast).
__device__ __forceinline__ void dot16x2p(const u64* a0, const u64* a1,
                                         const float* w, float bias,
                                         float& r0, float& r1) {
    const ulonglong2* w2 = reinterpret_cast<const ulonglong2*>(w);
    u64 acc0 = 0ull, acc1 = 0ull;
#pragma unroll
    for (int c = 0; c < 4; c++) {
        ulonglong2 wv = w2[c];
        acc0 = pfma(a0[2*c],   wv.x, acc0);
        acc1 = pfma(a1[2*c],   wv.x, acc1);
        acc0 = pfma(a0[2*c+1], wv.y, acc0);
        acc1 = pfma(a1[2*c+1], wv.y, acc1);
    }
    r0 = bias + hadd(acc0);
    r1 = bias + hadd(acc1);
}

// packed LayerNorm over 8 pairs (one token)
__device__ __forceinline__ void ln16p(const u64* y, const float* g,
                                      const float* b, u64* o) {
    u64 s01 = padd(padd(y[0], y[1]), padd(y[2], y[3]));
    u64 s23 = padd(padd(y[4], y[5]), padd(y[6], y[7]));
    float mu = hadd(padd(s01, s23)) * 0.0625f;
    u64 nmu = pk(-mu, -mu);
    u64 c[8];
    u64 v2 = 0ull;
#pragma unroll
    for (int dp = 0; dp < 8; dp++) {
        c[dp] = padd(y[dp], nmu);
        v2 = pfma(c[dp], c[dp], v2);
    }
    float rs = rsqrtf(fmaf(hadd(v2), 0.0625f, 1e-5f));
    u64 rs2 = pk(rs, rs);
    const ulonglong2* g2 = reinterpret_cast<const ulonglong2*>(g);
    const ulonglong2* b2 = reinterpret_cast<const ulonglong2*>(b);
#pragma unroll
    for (int q = 0; q < 4; q++) {
        ulonglong2 gv = g2[q], bv = b2[q];
        o[2*q]   = pfma(pmul(c[2*q],   rs2), gv.x, bv.x);
        o[2*q+1] = pfma(pmul(c[2*q+1], rs2), gv.y, bv.y);
    }
}

__global__ __launch_bounds__(NT, 2)
void ttb_kernel(const float* __restrict__ x,
                const float* __restrict__ Win,  const float* __restrict__ binp,
                const float* __restrict__ Wqkv, const float* __restrict__ bqkv,
                const float* __restrict__ Wo,   const float* __restrict__ bo,
                const float* __restrict__ ln1w, const float* __restrict__ ln1b,
                const float* __restrict__ W1,   const float* __restrict__ b1,
                const float* __restrict__ W2,   const float* __restrict__ b2,
                const float* __restrict__ ln2w, const float* __restrict__ ln2b,
                const float* __restrict__ Wout, const float* __restrict__ bout,
                float* __restrict__ out) {
    extern __shared__ float sm[];
    const int tid = threadIdx.x;

    // ---- stage weights (Q rows pre-scaled by 0.5*log2e; NOTE: % not &) ----
    for (int i = tid; i < 1536; i += NT) {
        float w = Wqkv[i];
        if (((i % 768) >> 4) < 16) w *= QSCALE;   // rows 0..15 of each layer = Q
        sm[OFF_WQKV + i] = w;
    }
    for (int i = tid; i < 96; i += NT) {
        float w = bqkv[i];
        if ((i % 48) < 16) w *= QSCALE;
        sm[OFF_BQKV + i] = w;
    }
    for (int i = tid; i <  512; i += NT) sm[OFF_WO   + i] = Wo[i];
    for (int i = tid; i <   32; i += NT) sm[OFF_BO   + i] = bo[i];
    for (int i = tid; i < 2048; i += NT) sm[OFF_W1   + i] = W1[i];
    for (int i = tid; i <  128; i += NT) sm[OFF_B1   + i] = b1[i];
    for (int i = tid; i < 2048; i += NT) {   // W2 [l][d][o] -> [l][o][d]
        int l = i >> 10, rem = i & 1023, o = rem >> 4, d = rem & 15;
        sm[OFF_W2T + i] = W2[l * 1024 + d * 64 + o];
    }
    for (int i = tid; i <   32; i += NT) sm[OFF_B2   + i] = b2[i];
    for (int i = tid; i <   32; i += NT) sm[OFF_LN1W + i] = ln1w[i];
    for (int i = tid; i <   32; i += NT) sm[OFF_LN1B + i] = ln1b[i];
    for (int i = tid; i <   32; i += NT) sm[OFF_LN2W + i] = ln2w[i];
    for (int i = tid; i <   32; i += NT) sm[OFF_LN2B + i] = ln2b[i];
    for (int i = tid; i <   16; i += NT) sm[OFF_WIN  + i] = Win[i];
    for (int i = tid; i <   16; i += NT) sm[OFF_BIN  + i] = binp[i];
    for (int i = tid; i <   16; i += NT) sm[OFF_WOUT + i] = Wout[i];
    if (tid == 0) sm[OFF_BOUT] = bout[0];

    // ---- stage this block's input pixels ----
    const int n0 = blockIdx.x * S;
    for (int i = tid; i < T * S; i += NT) {
        int t = i >> 4, c = i & 15;
        sm[OFF_XS + t * 17 + c] = x[t * HW + n0 + c];
    }
    __syncthreads();

    const int sl = tid / TPS;
    const int r  = tid % TPS;
    const int n  = n0 + sl;
    const int t0 = 2 * r;                 // tokens t0, t0+1

    // ---- input projection, h as d-pairs ----
    u64 hp0[8], hp1[8];
    {
        float xv0 = sm[OFF_XS + t0 * 17 + sl];
        float xv1 = sm[OFF_XS + (t0 + 1) * 17 + sl];
        u64 xp0 = pk(xv0, xv0), xp1 = pk(xv1, xv1);
        const ulonglong2* w2 = reinterpret_cast<const ulonglong2*>(&sm[OFF_WIN]);
        const ulonglong2* b2 = reinterpret_cast<const ulonglong2*>(&sm[OFF_BIN]);
#pragma unroll
        for (int c = 0; c < 4; c++) {
            ulonglong2 wv = w2[c], bv = b2[c];
            hp0[2*c]   = pfma(xp0, wv.x, bv.x);
            hp0[2*c+1] = pfma(xp0, wv.y, bv.y);
            hp1[2*c]   = pfma(xp1, wv.x, bv.x);
            hp1[2*c+1] = pfma(xp1, wv.y, bv.y);
        }
    }

    float* ksh = &sm[OFF_K + sl * KSEQ];
    float* vsh = &sm[OFF_V + sl * KSEQ];

#pragma unroll 1
    for (int l = 0; l < NL; l++) {
        const float* wqkv = &sm[OFF_WQKV + l * 768];
        const float* bq   = &sm[OFF_BQKV + l * 48];
        const float* wo   = &sm[OFF_WO   + l * 256];
        const float* bov  = &sm[OFF_BO   + l * 16];
        const float* w1   = &sm[OFF_W1   + l * 1024];
        const float* b1v  = &sm[OFF_B1   + l * 64];
        const float* w2t  = &sm[OFF_W2T  + l * 1024];
        const float* b2v  = &sm[OFF_B2   + l * 16];
        const float* g1w  = &sm[OFF_LN1W + l * 16];
        const float* g1b  = &sm[OFF_LN1B + l * 16];
        const float* g2w  = &sm[OFF_LN2W + l * 16];
        const float* g2b  = &sm[OFF_LN2B + l * 16];

        // ---- K,V projection -> SoA shared (row = head*4+d, col = s) ----
#pragma unroll 4
        for (int o = 0; o < D; o++) {       // K rows
            float r0, r1;
            dot16x2p(hp0, hp1, wqkv + (D + o) * D, bq[D + o], r0, r1);
            *reinterpret_cast<u64*>(&ksh[o * SROW + t0]) = pk(r0, r1);
        }
#pragma unroll 4
        for (int o = 0; o < D; o++) {       // V rows
            float r0, r1;
            dot16x2p(hp0, hp1, wqkv + (2 * D + o) * D, bq[2 * D + o], r0, r1);
            *reinterpret_cast<u64*>(&vsh[o * SROW + t0]) = pk(r0, r1);
        }
        __syncthreads();

        // ---- attention: row-major K/V reads via LDS.128 ----
        u64 cp0[8], cp1[8];
#pragma unroll
        for (int hd = 0; hd < NH; hd++) {
            // q for this head (Q weights pre-scaled: logits already log2 units)
            float q00, q01, q02, q03, q10, q11, q12, q13;
            dot16x2p(hp0, hp1, wqkv + (4*hd + 0) * D, bq[4*hd + 0], q00, q10);
            dot16x2p(hp0, hp1, wqkv + (4*hd + 1) * D, bq[4*hd + 1], q01, q11);
            dot16x2p(hp0, hp1, wqkv + (4*hd + 2) * D, bq[4*hd + 2], q02, q12);
            dot16x2p(hp0, hp1, wqkv + (4*hd + 3) * D, bq[4*hd + 3], q03, q13);
            const float* kb = ksh + hd * (4 * SROW);
            const float* vb = vsh + hd * (4 * SROW);
#pragma unroll
            for (int j = 0; j < 2; j++) {
                const u64 qp0 = j ? pk(q10, q10) : pk(q00, q00);
                const u64 qp1 = j ? pk(q11, q11) : pk(q01, q01);
                const u64 qp2 = j ? pk(q12, q12) : pk(q02, q02);
                const u64 qp3 = j ? pk(q13, q13) : pk(q03, q03);
                u64 lg[T / 2];
                // K pass, row-major: d=0 initializes, d=1..3 accumulate
                {
                    const ulonglong2* kr = reinterpret_cast<const ulonglong2*>(kb);
#pragma unroll
                    for (int c = 0; c < 6; c++) {
                        ulonglong2 kv = kr[c];
                        lg[2*c]   = pmul(qp0, kv.x);
                        lg[2*c+1] = pmul(qp0, kv.y);
                    }
                }
#pragma unroll
                for (int d = 1; d < 4; d++) {
                    const ulonglong2* kr =
                        reinterpret_cast<const ulonglong2*>(kb + d * SROW);
                    const u64 qd = (d == 1) ? qp1 : (d == 2) ? qp2 : qp3;
#pragma unroll
                    for (int c = 0; c < 6; c++) {
                        ulonglong2 kv = kr[c];
                        lg[2*c]   = pfma(qd, kv.x, lg[2*c]);
                        lg[2*c+1] = pfma(qd, kv.y, lg[2*c+1]);
                    }
                }
                // softmax in base-2 (Q pre-scaled), no max-subtraction
                u64 s2 = 0ull;
#pragma unroll
                for (int sp = 0; sp < T / 2; sp++) {
                    float a, b; unpk(lg[sp], a, b);
                    u64 e = pk(ex2f(a), ex2f(b));
                    lg[sp] = e;
                    s2 = padd(s2, e);
                }
                float inv = rcpf(hadd(s2));
                // V pass, row-major, 2 alternating accumulator chains per row
                float vt[4];
#pragma unroll
                for (int d = 0; d < 4; d++) {
                    const ulonglong2* vr =
                        reinterpret_cast<const ulonglong2*>(vb + d * SROW);
                    u64 aA = 0ull, aB = 0ull;
#pragma unroll
                    for (int c = 0; c < 6; c++) {
                        ulonglong2 vv = vr[c];
                        aA = pfma(lg[2*c],   vv.x, aA);
                        aB = pfma(lg[2*c+1], vv.y, aB);
                    }
                    vt[d] = hadd(padd(aA, aB)) * inv;
                }
                if (j == 0) {
                    cp0[2*hd]   = pk(vt[0], vt[1]);
                    cp0[2*hd+1] = pk(vt[2], vt[3]);
                } else {
                    cp1[2*hd]   = pk(vt[0], vt[1]);
                    cp1[2*hd+1] = pk(vt[2], vt[3]);
                }
            }
        }

        // ---- Wo projection + residual + LN1 ----
        {
            u64 y0[8], y1[8];
#pragma unroll
            for (int dp = 0; dp < 8; dp++) {
                float a0, a1, b0, b1_;
                dot16x2p(cp0, cp1, wo + (2*dp) * D,     bov[2*dp],     a0, a1);
                dot16x2p(cp0, cp1, wo + (2*dp + 1) * D, bov[2*dp + 1], b0, b1_);
                y0[dp] = padd(hp0[dp], pk(a0, b0));
                y1[dp] = padd(hp1[dp], pk(a1, b1_));
            }
            ln16p(y0, g1w, g1b, hp0);
            ln16p(y1, g1w, g1b, hp1);
        }

        // ---- FFN ----
        {
            u64 f0[8], f1[8];
            const ulonglong2* bb = reinterpret_cast<const ulonglong2*>(b2v);
#pragma unroll
            for (int q = 0; q < 4; q++) {
                ulonglong2 bv = bb[q];
                f0[2*q] = bv.x; f0[2*q+1] = bv.y;
                f1[2*q] = bv.x; f1[2*q+1] = bv.y;
            }
#pragma unroll 4
            for (int o = 0; o < DFF; o++) {
                float u0, u1;
                dot16x2p(hp0, hp1, w1 + o * D, b1v[o], u0, u1);
                u0 = fmaxf(u0, 0.f); u1 = fmaxf(u1, 0.f);
                u64 u0p = pk(u0, u0), u1p = pk(u1, u1);
                const ulonglong2* wr = reinterpret_cast<const ulonglong2*>(w2t + o * D);
#pragma unroll
                for (int c = 0; c < 4; c++) {
                    ulonglong2 wv = wr[c];
                    f0[2*c]   = pfma(u0p, wv.x, f0[2*c]);
                    f0[2*c+1] = pfma(u0p, wv.y, f0[2*c+1]);
                    f1[2*c]   = pfma(u1p, wv.x, f1[2*c]);
                    f1[2*c+1] = pfma(u1p, wv.y, f1[2*c+1]);
                }
            }
            u64 y0[8], y1[8];
#pragma unroll
            for (int dp = 0; dp < 8; dp++) {
                y0[dp] = padd(hp0[dp], f0[dp]);
                y1[dp] = padd(hp1[dp], f1[dp]);
            }
            ln16p(y0, g2w, g2b, hp0);
            ln16p(y1, g2w, g2b, hp1);
        }
        __syncthreads();   // K/V reuse by next layer
    }

    // ---- output projection ----
    {
        const ulonglong2* w2 = reinterpret_cast<const ulonglong2*>(&sm[OFF_WOUT]);
        u64 acc0 = 0ull, acc1 = 0ull;
#pragma unroll
        for (int c = 0; c < 4; c++) {
            ulonglong2 wv = w2[c];
            acc0 = pfma(hp0[2*c],   wv.x, acc0);
            acc0 = pfma(hp0[2*c+1], wv.y, acc0);
            acc1 = pfma(hp1[2*c],   wv.x, acc1);
            acc1 = pfma(hp1[2*c+1], wv.y, acc1);
        }
        float bo_ = sm[OFF_BOUT];
        out[t0 * HW + n]       = hadd(acc0) + bo_;
        out[(t0 + 1) * HW + n] = hadd(acc1) + bo_;
    }
}

extern "C" void kernel_launch(void* const* d_in, const int* in_sizes, int n_in,
                              void* d_out, int out_size) {
    (void)in_sizes; (void)n_in; (void)out_size;
    cudaFuncSetAttribute(ttb_kernel, cudaFuncAttributeMaxDynamicSharedMemorySize,
                         SMEM_BYTES);
    ttb_kernel<<<HW / S, NT, SMEM_BYTES>>>(
        (const float*)d_in[0],  (const float*)d_in[1],  (const float*)d_in[2],
        (const float*)d_in[3],  (const float*)d_in[4],  (const float*)d_in[5],
        (const float*)d_in[6],  (const float*)d_in[7],  (const float*)d_in[8],
        (const float*)d_in[9],  (const float*)d_in[10], (const float*)d_in[11],
        (const float*)d_in[12], (const float*)d_in[13], (const float*)d_in[14],
        (const float*)d_in[15], (const float*)d_in[16],
        (float*)d_out);
}

// round 17
// speedup vs baseline: 1.2810x; 1.0156x over previous
#include <cuda_runtime.h>

// TemporalTransformerBlock, fp32 + Blackwell packed f32x2.
// 65536 seqs, T=24, D=16, NH=4, HD=4, DFF=64, 2 layers.
// 12 threads/sequence, 2 tokens/thread; weights in smem (broadcast LDS);
// K/V SoA in smem. R3 structure with ILP chain-splitting:
// 4-chain dots, 2-chain softmax sum, 2-chain LN variance.

namespace {
constexpr int HW   = 256 * 256;
constexpr int T    = 24;
constexpr int D    = 16;
constexpr int NH   = 4;
constexpr int DFF  = 64;
constexpr int NL   = 2;
constexpr int S    = 16;          // sequences per block
constexpr int TPS  = 12;          // threads per sequence
constexpr int NT   = S * TPS;     // 192

constexpr float QSCALE = 0.7213475204444817f;   // 0.5 * log2(e)

// shared-memory float offsets
constexpr int OFF_WQKV = 0;                     // 1536
constexpr int OFF_BQKV = 1536;                  // 96
constexpr int OFF_WO   = 1632;                  // 512
constexpr int OFF_BO   = 2144;                  // 32
constexpr int OFF_W1   = 2176;                  // 2048
constexpr int OFF_B1   = 4224;                  // 128
constexpr int OFF_W2T  = 4352;                  // 2048 (W2 transposed [o][d])
constexpr int OFF_B2   = 6400;                  // 32
constexpr int OFF_LN1W = 6432;                  // 32
constexpr int OFF_LN1B = 6464;                  // 32
constexpr int OFF_LN2W = 6496;                  // 32
constexpr int OFF_LN2B = 6528;                  // 32
constexpr int OFF_WIN  = 6560;                  // 16
constexpr int OFF_BIN  = 6576;                  // 16
constexpr int OFF_WOUT = 6592;                  // 16
constexpr int OFF_BOUT = 6608;                  // 1 (+3 pad)
constexpr int OFF_XS   = 6612;                  // 24*17 = 408

// K/V SoA per sequence: row = head*4+d (16 rows), column = token s.
constexpr int SROW = 26;                        // padded row stride (even)
constexpr int KSEQ = 16 * SROW + 8;             // 424
constexpr int OFF_K = 7020;
constexpr int OFF_V = OFF_K + S * KSEQ;         // 13804
constexpr int SMEM_FLOATS = OFF_V + S * KSEQ;   // 20588
constexpr int SMEM_BYTES  = SMEM_FLOATS * 4;    // 82352
}

using u64 = unsigned long long;

__device__ __forceinline__ u64 pk(float lo, float hi) {
    u64 r; asm("mov.b64 %0, {%1, %2};" : "=l"(r) : "f"(lo), "f"(hi)); return r;
}
__device__ __forceinline__ void unpk(u64 p, float& lo, float& hi) {
    asm("mov.b64 {%0, %1}, %2;" : "=f"(lo), "=f"(hi) : "l"(p));
}
__device__ __forceinline__ u64 pfma(u64 a, u64 b, u64 c) {
    u64 d; asm("fma.rn.f32x2 %0, %1, %2, %3;" : "=l"(d) : "l"(a), "l"(b), "l"(c));
    return d;
}
__device__ __forceinline__ u64 padd(u64 a, u64 b) {
    u64 d; asm("add.rn.f32x2 %0, %1, %2;" : "=l"(d) : "l"(a), "l"(b)); return d;
}
__device__ __forceinline__ u64 pmul(u64 a, u64 b) {
    u64 d; asm("mul.rn.f32x2 %0, %1, %2;" : "=l"(d) : "l"(a), "l"(b)); return d;
}
__device__ __forceinline__ float hadd(u64 p) {
    float lo, hi; unpk(p, lo, hi); return lo + hi;
}
__device__ __forceinline__ float ex2f(float x) {
    float r; asm("ex2.approx.f32 %0, %1;" : "=f"(r) : "f"(x)); return r;
}
__device__ __forceinline__ float rcpf(float x) {
    float r; asm("rcp.approx.f32 %0, %1;" : "=f"(r) : "f"(x)); return r;
}

// two 16-dots (both tokens) against one shared weight row, 4 independent
// accumulator chains (max RAW depth 4 instead of 8).
__device__ __forceinline__ void dot16x2p(const u64* a0, const u64* a1,
                                         const float* w, float bias,
                                         float& r0, float& r1) {
    const ulonglong2* w2 = reinterpret_cast<const ulonglong2*>(w);
    ulonglong2 wv0 = w2[0], wv1 = w2[1], wv2 = w2[2], wv3 = w2[3];
    u64 a0a, a0b, a1a, a1b;
    a0a = pmul(a0[0], wv0.x);  a0b = pmul(a0[1], wv0.y);
    a1a = pmul(a1[0], wv0.x);  a1b = pmul(a1[1], wv0.y);
    a0a = pfma(a0[2], wv1.x, a0a);  a0b = pfma(a0[3], wv1.y, a0b);
    a1a = pfma(a1[2], wv1.x, a1a);  a1b = pfma(a1[3], wv1.y, a1b);
    a0a = pfma(a0[4], wv2.x, a0a);  a0b = pfma(a0[5], wv2.y, a0b);
    a1a = pfma(a1[4], wv2.x, a1a);  a1b = pfma(a1[5], wv2.y, a1b);
    a0a = pfma(a0[6], wv3.x, a0a);  a0b = pfma(a0[7], wv3.y, a0b);
    a1a = pfma(a1[6], wv3.x, a1a);  a1b = pfma(a1[7], wv3.y, a1b);
    r0 = bias + hadd(padd(a0a, a0b));
    r1 = bias + hadd(padd(a1a, a1b));
}

// packed LayerNorm over 8 pairs (one token); 2-chain variance.
__device__ __forceinline__ void ln16p(const u64* y, const float* g,
                                      const float* b, u64* o) {
    u64 s01 = padd(padd(y[0], y[1]), padd(y[2], y[3]));
    u64 s23 = padd(padd(y[4], y[5]), padd(y[6], y[7]));
    float mu = hadd(padd(s01, s23)) * 0.0625f;
    u64 nmu = pk(-mu, -mu);
    u64 c[8];
    u64 va = 0ull, vb = 0ull;
#pragma unroll
    for (int dp = 0; dp < 8; dp += 2) {
        c[dp]     = padd(y[dp], nmu);
        c[dp + 1] = padd(y[dp + 1], nmu);
        va = pfma(c[dp],     c[dp],     va);
        vb = pfma(c[dp + 1], c[dp + 1], vb);
    }
    float rs = rsqrtf(fmaf(hadd(padd(va, vb)), 0.0625f, 1e-5f));
    u64 rs2 = pk(rs, rs);
    const ulonglong2* g2 = reinterpret_cast<const ulonglong2*>(g);
    const ulonglong2* b2 = reinterpret_cast<const ulonglong2*>(b);
#pragma unroll
    for (int q = 0; q < 4; q++) {
        ulonglong2 gv = g2[q], bv = b2[q];
        o[2*q]   = pfma(pmul(c[2*q],   rs2), gv.x, bv.x);
        o[2*q+1] = pfma(pmul(c[2*q+1], rs2), gv.y, bv.y);
    }
}

__global__ __launch_bounds__(NT, 2)
void ttb_kernel(const float* __restrict__ x,
                const float* __restrict__ Win,  const float* __restrict__ binp,
                const float* __restrict__ Wqkv, const float* __restrict__ bqkv,
                const float* __restrict__ Wo,   const float* __restrict__ bo,
                const float* __restrict__ ln1w, const float* __restrict__ ln1b,
                const float* __restrict__ W1,   const float* __restrict__ b1,
                const float* __restrict__ W2,   const float* __restrict__ b2,
                const float* __restrict__ ln2w, const float* __restrict__ ln2b,
                const float* __restrict__ Wout, const float* __restrict__ bout,
                float* __restrict__ out) {
    extern __shared__ float sm[];
    const int tid = threadIdx.x;

    // ---- stage weights (Q rows pre-scaled by 0.5*log2e; NOTE: % not &) ----
    for (int i = tid; i < 1536; i += NT) {
        float w = Wqkv[i];
        if (((i % 768) >> 4) < 16) w *= QSCALE;   // rows 0..15 of each layer = Q
        sm[OFF_WQKV + i] = w;
    }
    for (int i = tid; i < 96; i += NT) {
        float w = bqkv[i];
        if ((i % 48) < 16) w *= QSCALE;
        sm[OFF_BQKV + i] = w;
    }
    for (int i = tid; i <  512; i += NT) sm[OFF_WO   + i] = Wo[i];
    for (int i = tid; i <   32; i += NT) sm[OFF_BO   + i] = bo[i];
    for (int i = tid; i < 2048; i += NT) sm[OFF_W1   + i] = W1[i];
    for (int i = tid; i <  128; i += NT) sm[OFF_B1   + i] = b1[i];
    for (int i = tid; i < 2048; i += NT) {   // W2 [l][d][o] -> [l][o][d]
        int l = i >> 10, rem = i & 1023, o = rem >> 4, d = rem & 15;
        sm[OFF_W2T + i] = W2[l * 1024 + d * 64 + o];
    }
    for (int i = tid; i <   32; i += NT) sm[OFF_B2   + i] = b2[i];
    for (int i = tid; i <   32; i += NT) sm[OFF_LN1W + i] = ln1w[i];
    for (int i = tid; i <   32; i += NT) sm[OFF_LN1B + i] = ln1b[i];
    for (int i = tid; i <   32; i += NT) sm[OFF_LN2W + i] = ln2w[i];
    for (int i = tid; i <   32; i += NT) sm[OFF_LN2B + i] = ln2b[i];
    for (int i = tid; i <   16; i += NT) sm[OFF_WIN  + i] = Win[i];
    for (int i = tid; i <   16; i += NT) sm[OFF_BIN  + i] = binp[i];
    for (int i = tid; i <   16; i += NT) sm[OFF_WOUT + i] = Wout[i];
    if (tid == 0) sm[OFF_BOUT] = bout[0];

    // ---- stage this block's input pixels ----
    const int n0 = blockIdx.x * S;
    for (int i = tid; i < T * S; i += NT) {
        int t = i >> 4, c = i & 15;
        sm[OFF_XS + t * 17 + c] = x[t * HW + n0 + c];
    }
    __syncthreads();

    const int sl = tid / TPS;
    const int r  = tid % TPS;
    const int n  = n0 + sl;
    const int t0 = 2 * r;                 // tokens t0, t0+1

    // ---- input projection, h as d-pairs ----
    u64 hp0[8], hp1[8];
    {
        float xv0 = sm[OFF_XS + t0 * 17 + sl];
        float xv1 = sm[OFF_XS + (t0 + 1) * 17 + sl];
        u64 xp0 = pk(xv0, xv0), xp1 = pk(xv1, xv1);
        const ulonglong2* w2 = reinterpret_cast<const ulonglong2*>(&sm[OFF_WIN]);
        const ulonglong2* b2 = reinterpret_cast<const ulonglong2*>(&sm[OFF_BIN]);
#pragma unroll
        for (int c = 0; c < 4; c++) {
            ulonglong2 wv = w2[c], bv = b2[c];
            hp0[2*c]   = pfma(xp0, wv.x, bv.x);
            hp0[2*c+1] = pfma(xp0, wv.y, bv.y);
            hp1[2*c]   = pfma(xp1, wv.x, bv.x);
            hp1[2*c+1] = pfma(xp1, wv.y, bv.y);
        }
    }

    float* ksh = &sm[OFF_K + sl * KSEQ];
    float* vsh = &sm[OFF_V + sl * KSEQ];

#pragma unroll 1
    for (int l = 0; l < NL; l++) {
        const float* wqkv = &sm[OFF_WQKV + l * 768];
        const float* bq   = &sm[OFF_BQKV + l * 48];
        const float* wo   = &sm[OFF_WO   + l * 256];
        const float* bov  = &sm[OFF_BO   + l * 16];
        const float* w1   = &sm[OFF_W1   + l * 1024];
        const float* b1v  = &sm[OFF_B1   + l * 64];
        const float* w2t  = &sm[OFF_W2T  + l * 1024];
        const float* b2v  = &sm[OFF_B2   + l * 16];
        const float* g1w  = &sm[OFF_LN1W + l * 16];
        const float* g1b  = &sm[OFF_LN1B + l * 16];
        const float* g2w  = &sm[OFF_LN2W + l * 16];
        const float* g2b  = &sm[OFF_LN2B + l * 16];

        // ---- K,V projection -> SoA shared (row = head*4+d, col = s) ----
#pragma unroll 4
        for (int o = 0; o < D; o++) {       // K rows
            float r0, r1;
            dot16x2p(hp0, hp1, wqkv + (D + o) * D, bq[D + o], r0, r1);
            *reinterpret_cast<u64*>(&ksh[o * SROW + t0]) = pk(r0, r1);
        }
#pragma unroll 4
        for (int o = 0; o < D; o++) {       // V rows
            float r0, r1;
            dot16x2p(hp0, hp1, wqkv + (2 * D + o) * D, bq[2 * D + o], r0, r1);
            *reinterpret_cast<u64*>(&vsh[o * SROW + t0]) = pk(r0, r1);
        }
        __syncthreads();

        // ---- attention (R3 structure) ----
        u64 cp0[8], cp1[8];
#pragma unroll
        for (int hd = 0; hd < NH; hd++) {
            // q for this head (Q weights pre-scaled: logits already log2 units)
            float q00, q01, q02, q03, q10, q11, q12, q13;
            dot16x2p(hp0, hp1, wqkv + (4*hd + 0) * D, bq[4*hd + 0], q00, q10);
            dot16x2p(hp0, hp1, wqkv + (4*hd + 1) * D, bq[4*hd + 1], q01, q11);
            dot16x2p(hp0, hp1, wqkv + (4*hd + 2) * D, bq[4*hd + 2], q02, q12);
            dot16x2p(hp0, hp1, wqkv + (4*hd + 3) * D, bq[4*hd + 3], q03, q13);
            const float* kb = ksh + hd * (4 * SROW);
            const float* vb = vsh + hd * (4 * SROW);
#pragma unroll
            for (int j = 0; j < 2; j++) {
                u64 qp0 = pk(j ? q10 : q00, j ? q10 : q00);
                u64 qp1 = pk(j ? q11 : q01, j ? q11 : q01);
                u64 qp2 = pk(j ? q12 : q02, j ? q12 : q02);
                u64 qp3 = pk(j ? q13 : q03, j ? q13 : q03);
                u64 lg[T / 2];
#pragma unroll
                for (int sp = 0; sp < T / 2; sp++) {
                    u64 k0 = *reinterpret_cast<const u64*>(kb + 2 * sp);
                    u64 k1 = *reinterpret_cast<const u64*>(kb + SROW + 2 * sp);
                    u64 k2 = *reinterpret_cast<const u64*>(kb + 2 * SROW + 2 * sp);
                    u64 k3 = *reinterpret_cast<const u64*>(kb + 3 * SROW + 2 * sp);
                    lg[sp] = pfma(qp0, k0, pfma(qp1, k1, pfma(qp2, k2, pmul(qp3, k3))));
                }
                // softmax in base-2 (Q pre-scaled), no max-subtraction;
                // 2-chain sum to halve the serial padd chain.
                u64 s2a = 0ull, s2b = 0ull;
#pragma unroll
                for (int sp = 0; sp < T / 2; sp += 2) {
                    float a, b;
                    unpk(lg[sp], a, b);
                    u64 e0 = pk(ex2f(a), ex2f(b));
                    lg[sp] = e0; s2a = padd(s2a, e0);
                    unpk(lg[sp + 1], a, b);
                    u64 e1 = pk(ex2f(a), ex2f(b));
                    lg[sp + 1] = e1; s2b = padd(s2b, e1);
                }
                float inv = rcpf(hadd(padd(s2a, s2b)));
                u64 c0 = 0ull, c1 = 0ull, c2 = 0ull, c3 = 0ull;
#pragma unroll
                for (int sp = 0; sp < T / 2; sp++) {
                    u64 v0 = *reinterpret_cast<const u64*>(vb + 2 * sp);
                    u64 v1 = *reinterpret_cast<const u64*>(vb + SROW + 2 * sp);
                    u64 v2 = *reinterpret_cast<const u64*>(vb + 2 * SROW + 2 * sp);
                    u64 v3 = *reinterpret_cast<const u64*>(vb + 3 * SROW + 2 * sp);
                    c0 = pfma(lg[sp], v0, c0);
                    c1 = pfma(lg[sp], v1, c1);
                    c2 = pfma(lg[sp], v2, c2);
                    c3 = pfma(lg[sp], v3, c3);
                }
                u64 pa = pk(hadd(c0) * inv, hadd(c1) * inv);
                u64 pb = pk(hadd(c2) * inv, hadd(c3) * inv);
                if (j == 0) { cp0[2*hd] = pa; cp0[2*hd+1] = pb; }
                else        { cp1[2*hd] = pa; cp1[2*hd+1] = pb; }
            }
        }

        // ---- Wo projection + residual + LN1 ----
        {
            u64 y0[8], y1[8];
#pragma unroll
            for (int dp = 0; dp < 8; dp++) {
                float a0, a1, b0, b1_;
                dot16x2p(cp0, cp1, wo + (2*dp) * D,     bov[2*dp],     a0, a1);
                dot16x2p(cp0, cp1, wo + (2*dp + 1) * D, bov[2*dp + 1], b0, b1_);
                y0[dp] = padd(hp0[dp], pk(a0, b0));
                y1[dp] = padd(hp1[dp], pk(a1, b1_));
            }
            ln16p(y0, g1w, g1b, hp0);
            ln16p(y1, g1w, g1b, hp1);
        }

        // ---- FFN ----
        {
            u64 f0[8], f1[8];
            const ulonglong2* bb = reinterpret_cast<const ulonglong2*>(b2v);
#pragma unroll
            for (int q = 0; q < 4; q++) {
                ulonglong2 bv = bb[q];
                f0[2*q] = bv.x; f0[2*q+1] = bv.y;
                f1[2*q] = bv.x; f1[2*q+1] = bv.y;
            }
#pragma unroll 4
            for (int o = 0; o < DFF; o++) {
                float u0, u1;
                dot16x2p(hp0, hp1, w1 + o * D, b1v[o], u0, u1);
                u0 = fmaxf(u0, 0.f); u1 = fmaxf(u1, 0.f);
                u64 u0p = pk(u0, u0), u1p = pk(u1, u1);
                const ulonglong2* wr = reinterpret_cast<const ulonglong2*>(w2t + o * D);
#pragma unroll
                for (int c = 0; c < 4; c++) {
                    ulonglong2 wv = wr[c];
                    f0[2*c]   = pfma(u0p, wv.x, f0[2*c]);
                    f0[2*c+1] = pfma(u0p, wv.y, f0[2*c+1]);
                    f1[2*c]   = pfma(u1p, wv.x, f1[2*c]);
                    f1[2*c+1] = pfma(u1p, wv.y, f1[2*c+1]);
                }
            }
            u64 y0[8], y1[8];
#pragma unroll
            for (int dp = 0; dp < 8; dp++) {
                y0[dp] = padd(hp0[dp], f0[dp]);
                y1[dp] = padd(hp1[dp], f1[dp]);
            }
            ln16p(y0, g2w, g2b, hp0);
            ln16p(y1, g2w, g2b, hp1);
        }
        __syncthreads();   // K/V reuse by next layer
    }

    // ---- output projection ----
    {
        const ulonglong2* w2 = reinterpret_cast<const ulonglong2*>(&sm[OFF_WOUT]);
        u64 acc0 = 0ull, acc1 = 0ull;
#pragma unroll
        for (int c = 0; c < 4; c++) {
            ulonglong2 wv = w2[c];
            acc0 = pfma(hp0[2*c],   wv.x, acc0);
            acc0 = pfma(hp0[2*c+1], wv.y, acc0);
            acc1 = pfma(hp1[2*c],   wv.x, acc1);
            acc1 = pfma(hp1[2*c+1], wv.y, acc1);
        }
        float bo_ = sm[OFF_BOUT];
        out[t0 * HW + n]       = hadd(acc0) + bo_;
        out[(t0 + 1) * HW + n] = hadd(acc1) + bo_;
    }
}

extern "C" void kernel_launch(void* const* d_in, const int* in_sizes, int n_in,
                              void* d_out, int out_size) {
    (void)in_sizes; (void)n_in; (void)out_size;
    cudaFuncSetAttribute(ttb_kernel, cudaFuncAttributeMaxDynamicSharedMemorySize,
                         SMEM_BYTES);
    ttb_kernel<<<HW / S, NT, SMEM_BYTES>>>(
        (const float*)d_in[0],  (const float*)d_in[1],  (const float*)d_in[2],
        (const float*)d_in[3],  (const float*)d_in[4],  (const float*)d_in[5],
        (const float*)d_in[6],  (const float*)d_in[7],  (const float*)d_in[8],
        (const float*)d_in[9],  (const float*)d_in[10], (const float*)d_in[11],
        (const float*)d_in[12], (const float*)d_in[13], (const float*)d_in[14],
        (const float*)d_in[15], (const float*)d_in[16],
        (float*)d_out);
}